// round 5
// baseline (speedup 1.0000x reference)
#include <cuda_runtime.h>
#include <math.h>

typedef unsigned long long ull;

#define T_STEPS 32
#define NN      1024
#define H       256
#define LDIM    128
#define V       800
#define BB      256
#define NB      15
#define E       (T_STEPS * NN)   /* 32768 */
#define R       (E + BB)         /* 33024 */
#define GRID_LOOP 148

// ---------------- device scratch ----------------
__device__ float g_hbuf[(E + 1) * H];
__device__ float g_Urh[(E + 1) * H];
__device__ float g_curo[(size_t)R * H];
__device__ float g_sh[NN * H];
__device__ float g_xg[NN * H];
__device__ float g_Epre[800 * 1024];   // [E_z|E_r|E_h|E_ui] per word, biases folded
__device__ float g_Xpu[BB * 512];      // [Xp|Xu] per context, biases folded
__device__ float g_Wcat[1024 * H];
__device__ float g_Wx[512 * LDIM];
__device__ float g_bcat[1024];
__device__ float g_bcat2[512];
__device__ float g_h2[(size_t)R * H];
__device__ float g_big[(size_t)R * V];
__device__ int   g_pidx[R];
__device__ int   g_pctx[R];
__device__ int   g_cnt;
__device__ float g_rowNll[R], g_rowHit[R], g_rowBce[R], g_rowSAcc[R];
__device__ unsigned g_barc;

// ---------------- f32x2 helpers ----------------
__device__ __forceinline__ ull pk2(float x, float y) {
    ull r; asm("mov.b64 %0,{%1,%2};" : "=l"(r) : "f"(x), "f"(y)); return r;
}
__device__ __forceinline__ void upk2(ull v, float& x, float& y) {
    asm("mov.b64 {%0,%1},%2;" : "=f"(x), "=f"(y) : "l"(v));
}
__device__ __forceinline__ ull ffma2(ull a, ull b, ull c) {
    ull d; asm("fma.rn.f32x2 %0,%1,%2,%3;" : "=l"(d) : "l"(a), "l"(b), "l"(c)); return d;
}

// ---------------- init ----------------
__global__ void k_init() {
    int j = threadIdx.x;
    if (blockIdx.x == 0) {
        g_hbuf[E * H + j] = 0.f;
        if (j == 0) g_barc = 0u;
    } else {
        g_Urh[E * H + j] = 0.f;
    }
}

// ---------------- build combined weights ----------------
__global__ void k_prep(const float* __restrict__ Wz, const float* __restrict__ Wzb,
                       const float* __restrict__ Wr, const float* __restrict__ Wrb,
                       const float* __restrict__ Wh, const float* __restrict__ Whb,
                       const float* __restrict__ Ui, const float* __restrict__ Uib,
                       const float* __restrict__ Ww, const float* __restrict__ Wb,
                       const float* __restrict__ Uw, const float* __restrict__ Ub) {
    int r = blockIdx.x, j = threadIdx.x;
    if (r < 1024) {
        int rr = r & 255;
        float v, b;
        if (r < 256)      { v = Wz[rr * 512 + j]; b = Wzb[rr]; }
        else if (r < 512) { v = Wr[rr * 256 + j]; b = Wrb[rr]; }
        else if (r < 768) { v = Wh[rr * 512 + j]; b = Whb[rr]; }
        else              { v = Ui[rr * 512 + j]; b = Uib[rr]; }
        g_Wcat[r * H + j] = v;
        if (j == 0) g_bcat[r] = b;
    } else {
        int r2 = r - 1024;
        int rr = r2 & 255;
        if (j < LDIM)
            g_Wx[r2 * LDIM + j] = (r2 < 256) ? Ww[rr * 384 + 256 + j] : Uw[rr * 384 + 256 + j];
        if (j == 0) g_bcat2[r2] = (r2 < 256) ? Wb[rr] : Ub[rr];
    }
}

// ---------------- head GEMM: 128x64 tile, f32x2 row-pair packing -----------
// EPI: 0=plain 1=+bias 2=relu(+addMat[id])   IM: 1 idxA[gr]; 2 split wid/root; 3 split ctx/identity
template <int EPI, int IM, bool GA>
__global__ void __launch_bounds__(256) k_hgemm(
    const float* __restrict__ A, int lda, int Mh, const int* __restrict__ Mptr,
    const float* __restrict__ W, int ldw, int Nc, int K,
    const float* __restrict__ bias, float* __restrict__ C, int ldc,
    const float* __restrict__ addMat, int addStride,
    const int* __restrict__ idxA, const int* __restrict__ idxB,
    const int* __restrict__ gidx) {
    const int M = Mptr ? *Mptr : Mh;
    const int bm = blockIdx.y * 128;
    if (bm >= M) return;
    const int bn = blockIdx.x * 64;
    __shared__ __align__(16) float sA[16][128];
    __shared__ __align__(16) float sWd[16][128];   // duplicated pairs
    const int tid = threadIdx.x;
    const int tx = tid & 15, ty = tid >> 4;
    ull acc[4][4];
#pragma unroll
    for (int i = 0; i < 4; i++)
#pragma unroll
        for (int j = 0; j < 4; j++) acc[i][j] = 0ULL;

    const int lr = tid >> 1, lk = (tid & 1) * 8;
    const int wr = tid >> 2, wk = (tid & 3) * 4;
    const bool wok = (bn + wr) < Nc;
    const float* Wp = W + (size_t)(bn + wr) * ldw + wk;
    const float* Ap = nullptr;
    bool aok = (bm + lr) < M;
    if (GA) {
        if (aok) {
            int pi = gidx[bm + lr];
            if (pi < BB) aok = false;
            else Ap = g_hbuf + (size_t)(pi - BB) * H + lk;
        }
    } else {
        Ap = A + (size_t)(bm + lr) * lda + lk;
    }

    for (int k0 = 0; k0 < K; k0 += 16) {
        float4 a0 = make_float4(0.f, 0.f, 0.f, 0.f), a1 = a0;
        if (aok) { a0 = *(const float4*)(Ap + k0); a1 = *(const float4*)(Ap + k0 + 4); }
        sA[lk + 0][lr] = a0.x; sA[lk + 1][lr] = a0.y; sA[lk + 2][lr] = a0.z; sA[lk + 3][lr] = a0.w;
        sA[lk + 4][lr] = a1.x; sA[lk + 5][lr] = a1.y; sA[lk + 6][lr] = a1.z; sA[lk + 7][lr] = a1.w;
        float4 w = wok ? *(const float4*)(Wp + k0) : make_float4(0.f, 0.f, 0.f, 0.f);
        *(ull*)&sWd[wk + 0][2 * wr] = pk2(w.x, w.x);
        *(ull*)&sWd[wk + 1][2 * wr] = pk2(w.y, w.y);
        *(ull*)&sWd[wk + 2][2 * wr] = pk2(w.z, w.z);
        *(ull*)&sWd[wk + 3][2 * wr] = pk2(w.w, w.w);
        __syncthreads();
#pragma unroll
        for (int k = 0; k < 16; k++) {
            ulonglong2 ap0 = *(const ulonglong2*)&sA[k][ty * 8];
            ulonglong2 ap1 = *(const ulonglong2*)&sA[k][ty * 8 + 4];
            ulonglong2 wp0 = *(const ulonglong2*)&sWd[k][tx * 8];
            ulonglong2 wp1 = *(const ulonglong2*)&sWd[k][tx * 8 + 4];
            acc[0][0] = ffma2(ap0.x, wp0.x, acc[0][0]); acc[0][1] = ffma2(ap0.x, wp0.y, acc[0][1]);
            acc[0][2] = ffma2(ap0.x, wp1.x, acc[0][2]); acc[0][3] = ffma2(ap0.x, wp1.y, acc[0][3]);
            acc[1][0] = ffma2(ap0.y, wp0.x, acc[1][0]); acc[1][1] = ffma2(ap0.y, wp0.y, acc[1][1]);
            acc[1][2] = ffma2(ap0.y, wp1.x, acc[1][2]); acc[1][3] = ffma2(ap0.y, wp1.y, acc[1][3]);
            acc[2][0] = ffma2(ap1.x, wp0.x, acc[2][0]); acc[2][1] = ffma2(ap1.x, wp0.y, acc[2][1]);
            acc[2][2] = ffma2(ap1.x, wp1.x, acc[2][2]); acc[2][3] = ffma2(ap1.x, wp1.y, acc[2][3]);
            acc[3][0] = ffma2(ap1.y, wp0.x, acc[3][0]); acc[3][1] = ffma2(ap1.y, wp0.y, acc[3][1]);
            acc[3][2] = ffma2(ap1.y, wp1.x, acc[3][2]); acc[3][3] = ffma2(ap1.y, wp1.y, acc[3][3]);
        }
        __syncthreads();
    }

    const int gc0 = bn + tx * 4;
    if (gc0 >= Nc) return;
#pragma unroll
    for (int i = 0; i < 4; i++) {
        int r0 = bm + ty * 8 + 2 * i;
#pragma unroll
        for (int half = 0; half < 2; half++) {
            int gr = r0 + half;
            if (gr >= M) continue;
            float v[4];
#pragma unroll
            for (int j = 0; j < 4; j++) {
                float lo, hi; upk2(acc[i][j], lo, hi);
                v[j] = half ? hi : lo;
            }
            if (EPI == 1) {
#pragma unroll
                for (int j = 0; j < 4; j++) v[j] += bias[gc0 + j];
            } else if (EPI == 2) {
                int id;
                if (IM == 1)      id = idxA[gr];
                else if (IM == 2) id = (gr < E) ? idxA[gr] : idxB[gr - E];
                else              id = (gr < E) ? idxA[gr] : (gr - E);
                const float* am = addMat + (size_t)id * addStride + gc0;
#pragma unroll
                for (int j = 0; j < 4; j++) v[j] = fmaxf(v[j] + am[j], 0.f);
            }
            *(float4*)&C[(size_t)gr * ldc + gc0] = make_float4(v[0], v[1], v[2], v[3]);
        }
    }
}

// ---------------- software grid barrier ----------------
__device__ __forceinline__ void gbar(unsigned& target) {
    __syncthreads();
    target += GRID_LOOP;
    if (threadIdx.x == 0) {
        __threadfence();                       // release (orders CTA writes via bar cumulativity)
        atomicAdd(&g_barc, 1u);
        while (*(volatile unsigned*)&g_barc < target) __nanosleep(20);
        __threadfence();                       // acquire + L1 invalidate (CCTL.IVALL)
    }
    __syncthreads();
}

// ---------------- persistent recurrent loop ----------------
__global__ void __launch_bounds__(256, 1) k_loop(
    const int* __restrict__ word_ids, const int* __restrict__ h_nei,
    const int* __restrict__ o_nei,
    const float* __restrict__ Wz, const float* __restrict__ Wh,  // h-part, ldw 512
    const float* __restrict__ Urw) {
    __shared__ __align__(16) float sA1[16][64];
    __shared__ __align__(16) float sA2[16][64];
    __shared__ __align__(16) float sW1[16][64];   // duplicated pairs (32 cols)
    __shared__ __align__(16) float sW2[16][64];
    const int tid = threadIdx.x;
    unsigned target = 0;

    for (int t = 0; t < T_STEPS; t++) {
        // ---- phase 1: gather (sum_h, gated, cur_o) ----
        for (int n = blockIdx.x; n < NN; n += GRID_LOOP) {
            int base = t * NN + n;
            int wid = word_ids[base];
            float rx = g_Epre[(size_t)wid * 1024 + 256 + tid];
            const int* hrow = h_nei + base * NB;
            const int* orow = o_nei + base * NB;
            float sh = 0.f, g = 0.f, co = 0.f;
#pragma unroll
            for (int nb = 0; nb < NB; nb++) {
                int hi = hrow[nb];
                float v  = g_hbuf[(size_t)hi * H + tid];
                float rp = g_Urh[(size_t)hi * H + tid];
                sh += v;
                g  += v / (1.f + expf(-(rx + rp)));
            }
#pragma unroll
            for (int nb = 0; nb < NB; nb++) co += g_hbuf[(size_t)orow[nb] * H + tid];
            g_sh[n * H + tid] = sh;
            g_xg[n * H + tid] = g;
            g_curo[(size_t)base * H + tid] = co;
        }
        gbar(target);

        // ---- phase 2: fused z/h GEMM + GRU combine (tiles 64x32, 128 tiles) ----
        float* hout = g_hbuf + (size_t)t * NN * H;
        for (int tile = blockIdx.x; tile < 128; tile += GRID_LOOP) {
            const int bm = (tile >> 3) * 64, bn = (tile & 7) * 32;
            const int tx = tid & 7, ty = tid >> 3;          // ty 0..31
            ull accZ[4] = {0, 0, 0, 0}, accH[4] = {0, 0, 0, 0};
            const int lr = tid >> 2, lk = (tid & 3) << 2;
            const int wwr = (tid & 127) >> 2, wwk = (tid & 3) << 2;
            const float* Wp = ((tid < 128) ? Wz : Wh) + (size_t)(bn + wwr) * 512 + wwk;
            float (*sWd)[64] = (tid < 128) ? sW1 : sW2;
            const float* A1p = g_sh + (size_t)(bm + lr) * H + lk;
            const float* A2p = g_xg + (size_t)(bm + lr) * H + lk;
            for (int k0 = 0; k0 < H; k0 += 16) {
                float4 a1 = *(const float4*)(A1p + k0);
                float4 a2 = *(const float4*)(A2p + k0);
                float4 w  = *(const float4*)(Wp + k0);
                sA1[lk + 0][lr] = a1.x; sA1[lk + 1][lr] = a1.y; sA1[lk + 2][lr] = a1.z; sA1[lk + 3][lr] = a1.w;
                sA2[lk + 0][lr] = a2.x; sA2[lk + 1][lr] = a2.y; sA2[lk + 2][lr] = a2.z; sA2[lk + 3][lr] = a2.w;
                *(ull*)&sWd[wwk + 0][2 * wwr] = pk2(w.x, w.x);
                *(ull*)&sWd[wwk + 1][2 * wwr] = pk2(w.y, w.y);
                *(ull*)&sWd[wwk + 2][2 * wwr] = pk2(w.z, w.z);
                *(ull*)&sWd[wwk + 3][2 * wwr] = pk2(w.w, w.w);
                __syncthreads();
#pragma unroll
                for (int k = 0; k < 16; k++) {
                    ull a1p = *(const ull*)&sA1[k][ty * 2];
                    ull a2p = *(const ull*)&sA2[k][ty * 2];
                    ulonglong2 w1a = *(const ulonglong2*)&sW1[k][tx * 8];
                    ulonglong2 w1b = *(const ulonglong2*)&sW1[k][tx * 8 + 4];
                    ulonglong2 w2a = *(const ulonglong2*)&sW2[k][tx * 8];
                    ulonglong2 w2b = *(const ulonglong2*)&sW2[k][tx * 8 + 4];
                    accZ[0] = ffma2(a1p, w1a.x, accZ[0]); accZ[1] = ffma2(a1p, w1a.y, accZ[1]);
                    accZ[2] = ffma2(a1p, w1b.x, accZ[2]); accZ[3] = ffma2(a1p, w1b.y, accZ[3]);
                    accH[0] = ffma2(a2p, w2a.x, accH[0]); accH[1] = ffma2(a2p, w2a.y, accH[1]);
                    accH[2] = ffma2(a2p, w2b.x, accH[2]); accH[3] = ffma2(a2p, w2b.y, accH[3]);
                }
                __syncthreads();
            }
            const int r0 = bm + ty * 2;
            int w0 = word_ids[t * NN + r0], w1 = word_ids[t * NN + r0 + 1];
            const float* e0 = g_Epre + (size_t)w0 * 1024;
            const float* e1 = g_Epre + (size_t)w1 * 1024;
            float o0[4], o1[4];
#pragma unroll
            for (int j = 0; j < 4; j++) {
                int c = bn + tx * 4 + j;
                float zl, zh, hl, hh;
                upk2(accZ[j], zl, zh); upk2(accH[j], hl, hh);
                float z0 = 1.f / (1.f + expf(-(zl + e0[c])));
                float z1 = 1.f / (1.f + expf(-(zh + e1[c])));
                float t0 = tanhf(hl + e0[512 + c]);
                float t1 = tanhf(hh + e1[512 + c]);
                o0[j] = (1.f - z0) * g_sh[(size_t)r0 * H + c] + z0 * t0;
                o1[j] = (1.f - z1) * g_sh[(size_t)(r0 + 1) * H + c] + z1 * t1;
            }
            *(float4*)&hout[(size_t)r0 * H + bn + tx * 4]       = make_float4(o0[0], o0[1], o0[2], o0[3]);
            *(float4*)&hout[(size_t)(r0 + 1) * H + bn + tx * 4] = make_float4(o1[0], o1[1], o1[2], o1[3]);
        }
        gbar(target);

        // ---- phase 3: Urh(t) = newh @ Ur^T (tiles 64x32, 128 tiles) ----
        float* uout = g_Urh + (size_t)t * NN * H;
        for (int tile = blockIdx.x; tile < 128; tile += GRID_LOOP) {
            const int bm = (tile >> 3) * 64, bn = (tile & 7) * 32;
            const int tx = tid & 7, ty = tid >> 3;
            ull acc[4] = {0, 0, 0, 0};
            const int lr = tid >> 2, lk = (tid & 3) << 2;
            const int wwr = (tid & 127) >> 2, wwk = (tid & 3) << 2;
            const float* Ap = hout + (size_t)(bm + lr) * H + lk;
            const float* Wp = Urw + (size_t)(bn + wwr) * H + wwk;
            for (int k0 = 0; k0 < H; k0 += 16) {
                float4 a = *(const float4*)(Ap + k0);
                sA1[lk + 0][lr] = a.x; sA1[lk + 1][lr] = a.y; sA1[lk + 2][lr] = a.z; sA1[lk + 3][lr] = a.w;
                if (tid < 128) {
                    float4 w = *(const float4*)(Wp + k0);
                    *(ull*)&sW1[wwk + 0][2 * wwr] = pk2(w.x, w.x);
                    *(ull*)&sW1[wwk + 1][2 * wwr] = pk2(w.y, w.y);
                    *(ull*)&sW1[wwk + 2][2 * wwr] = pk2(w.z, w.z);
                    *(ull*)&sW1[wwk + 3][2 * wwr] = pk2(w.w, w.w);
                }
                __syncthreads();
#pragma unroll
                for (int k = 0; k < 16; k++) {
                    ull ap = *(const ull*)&sA1[k][ty * 2];
                    ulonglong2 wa = *(const ulonglong2*)&sW1[k][tx * 8];
                    ulonglong2 wb = *(const ulonglong2*)&sW1[k][tx * 8 + 4];
                    acc[0] = ffma2(ap, wa.x, acc[0]); acc[1] = ffma2(ap, wa.y, acc[1]);
                    acc[2] = ffma2(ap, wb.x, acc[2]); acc[3] = ffma2(ap, wb.y, acc[3]);
                }
                __syncthreads();
            }
            const int r0 = bm + ty * 2;
            float o0[4], o1[4];
#pragma unroll
            for (int j = 0; j < 4; j++) { upk2(acc[j], o0[j], o1[j]); }
            *(float4*)&uout[(size_t)r0 * H + bn + tx * 4]       = make_float4(o0[0], o0[1], o0[2], o0[3]);
            *(float4*)&uout[(size_t)(r0 + 1) * H + bn + tx * 4] = make_float4(o1[0], o1[1], o1[2], o1[3]);
        }
        gbar(target);
    }
}

// ---------------- compact pred rows ----------------
__global__ void k_compact(const int* __restrict__ direction, const int* __restrict__ contexts) {
    __shared__ int warpsum[32];
    __shared__ int sbase;
    int tid = threadIdx.x, lane = tid & 31, w = tid >> 5;
    if (tid == 0) sbase = 0;
    __syncthreads();
    for (int chunk = 0; chunk < R; chunk += 1024) {
        int i = chunk + tid;
        int m = 0;
        if (i < R) m = (i < BB) ? 1 : (direction[i - BB] != 0);
        unsigned bal = __ballot_sync(0xffffffffu, m);
        int pre = __popc(bal & ((1u << lane) - 1u));
        if (lane == 0) warpsum[w] = __popc(bal);
        __syncthreads();
        if (tid < 32) {
            int v = warpsum[tid];
#pragma unroll
            for (int off = 1; off < 32; off <<= 1) {
                int o = __shfl_up_sync(0xffffffffu, v, off);
                if (tid >= off) v += o;
            }
            warpsum[tid] = v;
        }
        __syncthreads();
        int wbase = (w == 0) ? 0 : warpsum[w - 1];
        if (m) {
            int pos = sbase + wbase + pre;
            g_pidx[pos] = i;
            g_pctx[pos] = (i < BB) ? i : contexts[i - BB];
        }
        __syncthreads();
        if (tid == 0) sbase += warpsum[31];
        __syncthreads();
    }
    if (tid == 0) g_cnt = sbase;
}

// ---------------- pred row reduction ----------------
__global__ void k_predReduce(const int* __restrict__ pred_targets,
                             const int* __restrict__ root_word_ids) {
    int w = threadIdx.x >> 5, lane = threadIdx.x & 31;
    int r = blockIdx.x * 8 + w;
    if (r >= g_cnt) return;
    int gi = g_pidx[r];
    const float* row = g_big + (size_t)r * V;
    float bv = -INFINITY; int bi = 0x7fffffff;
    for (int j = lane; j < V; j += 32) {
        float v = row[j];
        if (v > bv) { bv = v; bi = j; }
    }
#pragma unroll
    for (int off = 16; off; off >>= 1) {
        float ov = __shfl_xor_sync(0xffffffffu, bv, off);
        int   oi = __shfl_xor_sync(0xffffffffu, bi, off);
        if (ov > bv || (ov == bv && oi < bi)) { bv = ov; bi = oi; }
    }
    float s = 0.f;
    for (int j = lane; j < V; j += 32) s += expf(row[j] - bv);
#pragma unroll
    for (int off = 16; off; off >>= 1) s += __shfl_xor_sync(0xffffffffu, s, off);
    if (lane == 0) {
        int tgt = (gi < BB) ? root_word_ids[gi] : pred_targets[gi - BB];
        g_rowNll[r] = bv + logf(s) - row[tgt];
        g_rowHit[r] = (bi == tgt) ? 1.f : 0.f;
    }
}

// ---------------- stop-head root cur_o ----------------
__global__ void k_stopRoot(const int* __restrict__ root_o_idx) {
    int b = blockIdx.x, j = threadIdx.x;
    float s = 0.f;
#pragma unroll
    for (int nb = 0; nb < NB; nb++) s += g_hbuf[(size_t)root_o_idx[b * NB + nb] * H + j];
    g_curo[(size_t)(E + b) * H + j] = s;
}

// ---------------- stop scalar dot + bce ----------------
__global__ void k_stopDot(const float* __restrict__ Uo_w, const float* __restrict__ Uo_b,
                          const int* __restrict__ direction) {
    int w = threadIdx.x >> 5, lane = threadIdx.x & 31;
    int gi = blockIdx.x * 8 + w;
    if (gi >= R) return;
    const float* row = g_big + (size_t)gi * H;
    float s = 0.f;
#pragma unroll
    for (int k = lane; k < H; k += 32) s += row[k] * Uo_w[k];
#pragma unroll
    for (int off = 16; off; off >>= 1) s += __shfl_xor_sync(0xffffffffu, s, off);
    if (lane == 0) {
        s += Uo_b[0];
        float tgt = (gi < E) ? (float)direction[gi] : 0.f;
        g_rowBce[gi] = fmaxf(s, 0.f) - s * tgt + log1pf(expf(-fabsf(s)));
        float pred = (s >= 0.f) ? 1.f : 0.f;
        g_rowSAcc[gi] = (pred == tgt) ? 1.f : 0.f;
    }
}

// ---------------- final reduction ----------------
__global__ void k_final(float* __restrict__ out) {
    __shared__ float sm[1024];
    int tid = threadIdx.x;
    int cnt = g_cnt;
    float a0 = 0.f, a1 = 0.f, a3 = 0.f, a4 = 0.f;
    for (int i = tid; i < cnt; i += 1024) { a0 += g_rowNll[i]; a1 += g_rowHit[i]; }
    for (int i = tid; i < R; i += 1024)   { a3 += g_rowBce[i]; a4 += g_rowSAcc[i]; }
    auto red = [&](float v) -> float {
        sm[tid] = v; __syncthreads();
        for (int s = 512; s; s >>= 1) { if (tid < s) sm[tid] += sm[tid + s]; __syncthreads(); }
        float r = sm[0]; __syncthreads();
        return r;
    };
    float nll = red(a0), hit = red(a1), bce = red(a3), sac = red(a4);
    if (tid == 0) {
        out[0] = nll / (float)BB;
        out[1] = bce / (float)BB;
        out[2] = hit / (float)cnt;
        out[3] = sac / (float)R;
    }
}

// ---------------- launch ----------------
extern "C" void kernel_launch(void* const* d_in, const int* in_sizes, int n_in,
                              void* d_out, int out_size) {
    const float* emb    = (const float*)d_in[0];
    const float* W_z_w  = (const float*)d_in[1];
    const float* W_z_b  = (const float*)d_in[2];
    const float* W_r_w  = (const float*)d_in[3];
    const float* W_r_b  = (const float*)d_in[4];
    const float* U_r_w  = (const float*)d_in[5];
    const float* W_h_w  = (const float*)d_in[6];
    const float* W_h_b  = (const float*)d_in[7];
    const float* W_w    = (const float*)d_in[8];
    const float* W_b    = (const float*)d_in[9];
    const float* Wo_w   = (const float*)d_in[10];
    const float* Wo_b   = (const float*)d_in[11];
    const float* U_w    = (const float*)d_in[12];
    const float* U_b    = (const float*)d_in[13];
    const float* Ui_w   = (const float*)d_in[14];
    const float* Ui_b   = (const float*)d_in[15];
    const float* Uo_w   = (const float*)d_in[16];
    const float* Uo_b   = (const float*)d_in[17];
    const float* xtree  = (const float*)d_in[18];
    const int* word_ids = (const int*)d_in[19];
    const int* h_nei    = (const int*)d_in[20];
    const int* o_nei    = (const int*)d_in[21];
    const int* contexts = (const int*)d_in[22];
    const int* pred_t   = (const int*)d_in[23];
    const int* directn  = (const int*)d_in[24];
    const int* root_wid = (const int*)d_in[25];
    const int* root_oid = (const int*)d_in[26];
    float* out = (float*)d_out;

    float *p_Epre, *p_Xpu, *p_Wcat, *p_Wx, *p_bcat, *p_bcat2, *p_h2, *p_big, *p_curo;
    int *p_cnt, *p_pctx, *p_pidx;
    cudaGetSymbolAddress((void**)&p_Epre, g_Epre);
    cudaGetSymbolAddress((void**)&p_Xpu, g_Xpu);
    cudaGetSymbolAddress((void**)&p_Wcat, g_Wcat);
    cudaGetSymbolAddress((void**)&p_Wx, g_Wx);
    cudaGetSymbolAddress((void**)&p_bcat, g_bcat);
    cudaGetSymbolAddress((void**)&p_bcat2, g_bcat2);
    cudaGetSymbolAddress((void**)&p_h2, g_h2);
    cudaGetSymbolAddress((void**)&p_big, g_big);
    cudaGetSymbolAddress((void**)&p_curo, g_curo);
    cudaGetSymbolAddress((void**)&p_cnt, g_cnt);
    cudaGetSymbolAddress((void**)&p_pctx, g_pctx);
    cudaGetSymbolAddress((void**)&p_pidx, g_pidx);

    // ---- one-time precomputes ----
    k_init<<<2, 256>>>();
    k_prep<<<1536, 256>>>(W_z_w, W_z_b, W_r_w, W_r_b, W_h_w, W_h_b, Ui_w, Ui_b,
                          W_w, W_b, U_w, U_b);
    // Epre = emb @ Wcat^T + bcat    (800 x 1024)
    k_hgemm<1, 0, false><<<dim3(16, 7), 256>>>(emb, H, 800, nullptr, p_Wcat, H, 1024, H,
                                               p_bcat, p_Epre, 1024, nullptr, 0,
                                               nullptr, nullptr, nullptr);
    // Xpu = xtree @ Wx^T + bcat2    (256 x 512)
    k_hgemm<1, 0, false><<<dim3(8, 2), 256>>>(xtree, LDIM, BB, nullptr, p_Wx, LDIM, 512, LDIM,
                                              p_bcat2, p_Xpu, 512, nullptr, 0,
                                              nullptr, nullptr, nullptr);

    // ---- persistent recurrent loop (one kernel, 96 internal grid barriers) ----
    k_loop<<<GRID_LOOP, 256>>>(word_ids, h_nei, o_nei, W_z_w + 256, W_h_w + 256, U_r_w);

    // ---- word prediction head (mask-compacted, gathered A) ----
    k_compact<<<1, 1024>>>(directn, contexts);
    k_hgemm<2, 1, true><<<dim3(4, 259), 256>>>(nullptr, H, R, p_cnt, W_w, 384, H, H,
                                               nullptr, p_h2, H, p_Xpu, 512,
                                               p_pctx, nullptr, p_pidx);
    k_hgemm<1, 0, false><<<dim3(13, 259), 256>>>(p_h2, H, R, p_cnt, Wo_w, H, V, H,
                                                 Wo_b, p_big, V, nullptr, 0,
                                                 nullptr, nullptr, nullptr);
    k_predReduce<<<(R + 7) / 8, 256>>>(pred_t, root_wid);

    // ---- stop head ----
    k_stopRoot<<<BB, 256>>>(root_oid);
    k_hgemm<2, 2, false><<<dim3(4, 258), 256>>>(p_curo, H, R, nullptr, Ui_w + 256, 512, H, H,
                                                nullptr, p_h2, H, p_Epre + 768, 1024,
                                                word_ids, root_wid, nullptr);
    k_hgemm<2, 3, false><<<dim3(4, 258), 256>>>(p_h2, H, R, nullptr, U_w, 384, H, H,
                                                nullptr, p_big, H, p_Xpu + 256, 512,
                                                contexts, nullptr, nullptr);
    k_stopDot<<<(R + 7) / 8, 256>>>(Uo_w, Uo_b, directn);

    k_final<<<1, 1024>>>(out);
}

// round 6
// speedup vs baseline: 1.4800x; 1.4800x over previous
#include <cuda_runtime.h>
#include <math.h>

#define T_STEPS 32
#define NN      1024
#define H       256
#define LDIM    128
#define V       800
#define BB      256
#define NB      15
#define E       (T_STEPS * NN)   /* 32768 */
#define R       (E + BB)         /* 33024 */
#define GRID_LOOP 128

// ---------------- device scratch ----------------
__device__ float g_hbuf[(E + 1) * H];
__device__ float g_Urh[(E + 1) * H];
__device__ float g_curo[(size_t)R * H];
__device__ float g_sh[NN * H];
__device__ float g_xg[NN * H];
__device__ float g_Epre[800 * 1024];   // [E_z|E_r|E_h|E_ui] per word, biases folded
__device__ float g_Xpu[BB * 512];      // [Xp|Xu] per context, biases folded
__device__ float g_Wcat[1024 * H];
__device__ float g_Wx[512 * LDIM];
__device__ float g_bcat[1024];
__device__ float g_bcat2[512];
__device__ float g_Ac[(size_t)R * H];
__device__ float g_h2[(size_t)R * H];
__device__ float g_big[(size_t)R * V];
__device__ int   g_pidx[R];
__device__ int   g_pctx[R];
__device__ int   g_swid[R];
__device__ int   g_sctx[R];
__device__ int   g_cnt;
__device__ float g_rowNll[R], g_rowHit[R], g_rowBce[R], g_rowSAcc[R];
__device__ unsigned g_barc;

// ---------------- init ----------------
__global__ void k_init() {
    int j = threadIdx.x;
    if (blockIdx.x == 0) {
        g_hbuf[E * H + j] = 0.f;
        if (j == 0) g_barc = 0u;
    } else {
        g_Urh[E * H + j] = 0.f;
    }
}

// ---------------- build combined weights ----------------
__global__ void k_prep(const float* __restrict__ Wz, const float* __restrict__ Wzb,
                       const float* __restrict__ Wr, const float* __restrict__ Wrb,
                       const float* __restrict__ Wh, const float* __restrict__ Whb,
                       const float* __restrict__ Ui, const float* __restrict__ Uib,
                       const float* __restrict__ Ww, const float* __restrict__ Wb,
                       const float* __restrict__ Uw, const float* __restrict__ Ub) {
    int r = blockIdx.x, j = threadIdx.x;
    if (r < 1024) {
        int rr = r & 255;
        float v, b;
        if (r < 256)      { v = Wz[rr * 512 + j]; b = Wzb[rr]; }
        else if (r < 512) { v = Wr[rr * 256 + j]; b = Wrb[rr]; }
        else if (r < 768) { v = Wh[rr * 512 + j]; b = Whb[rr]; }
        else              { v = Ui[rr * 512 + j]; b = Uib[rr]; }
        g_Wcat[r * H + j] = v;
        if (j == 0) g_bcat[r] = b;
    } else {
        int r2 = r - 1024;
        int rr = r2 & 255;
        if (j < LDIM)
            g_Wx[r2 * LDIM + j] = (r2 < 256) ? Ww[rr * 384 + 256 + j] : Uw[rr * 384 + 256 + j];
        if (j == 0) g_bcat2[r2] = (r2 < 256) ? Wb[rr] : Ub[rr];
    }
}

// ---------------- generic fp32 GEMM (R3-proven): C = epi(A @ W^T) ----------
// EPI: 0=plain  1=+bias  2=relu(+addMat[addIdx[row]])
template <int BM, int EPI>
__global__ void __launch_bounds__(256) k_gemm(
    const float* __restrict__ A, int lda, int Mh, const int* __restrict__ Mptr,
    const float* __restrict__ W, int ldw, int Nc, int K,
    const float* __restrict__ bias,
    float* __restrict__ C, int ldc,
    const float* __restrict__ addMat, int addStride, const int* __restrict__ addIdx) {
    const int M = Mptr ? *Mptr : Mh;
    const int bm = blockIdx.y * BM;
    if (bm >= M) return;
    const int bn = blockIdx.x * 64;
    __shared__ __align__(16) float sA[16][BM];
    __shared__ __align__(16) float sW[16][64];
    const int tid = threadIdx.x;
    constexpr int TM = BM / 16;
    const int tx = tid & 15, ty = tid >> 4;
    float acc[TM][4];
#pragma unroll
    for (int i = 0; i < TM; i++)
#pragma unroll
        for (int j = 0; j < 4; j++) acc[i][j] = 0.f;
    const int lr = tid >> 2, lk = (tid & 3) << 2;
    const bool wok = (bn + lr) < Nc;
    const bool aok = (lr < BM) && ((bm + lr) < M);
    const float* Wp = W + (size_t)(bn + lr) * ldw + lk;
    const float* Ap = A + (size_t)(bm + (lr < BM ? lr : 0)) * lda + lk;

    for (int k0 = 0; k0 < K; k0 += 16) {
        float4 w = wok ? *(const float4*)(Wp + k0) : make_float4(0.f, 0.f, 0.f, 0.f);
        sW[lk + 0][lr] = w.x; sW[lk + 1][lr] = w.y; sW[lk + 2][lr] = w.z; sW[lk + 3][lr] = w.w;
        if (lr < BM) {
            float4 a = aok ? *(const float4*)(Ap + k0) : make_float4(0.f, 0.f, 0.f, 0.f);
            sA[lk + 0][lr] = a.x; sA[lk + 1][lr] = a.y; sA[lk + 2][lr] = a.z; sA[lk + 3][lr] = a.w;
        }
        __syncthreads();
#pragma unroll
        for (int k = 0; k < 16; k++) {
            float4 wv = *(const float4*)&sW[k][tx * 4];
            if constexpr (TM == 4) {
                float4 av = *(const float4*)&sA[k][ty * 4];
                acc[0][0] += av.x * wv.x; acc[0][1] += av.x * wv.y; acc[0][2] += av.x * wv.z; acc[0][3] += av.x * wv.w;
                acc[1][0] += av.y * wv.x; acc[1][1] += av.y * wv.y; acc[1][2] += av.y * wv.z; acc[1][3] += av.y * wv.w;
                acc[2][0] += av.z * wv.x; acc[2][1] += av.z * wv.y; acc[2][2] += av.z * wv.z; acc[2][3] += av.z * wv.w;
                acc[3][0] += av.w * wv.x; acc[3][1] += av.w * wv.y; acc[3][2] += av.w * wv.z; acc[3][3] += av.w * wv.w;
            } else {
                float2 av = *(const float2*)&sA[k][ty * 2];
                acc[0][0] += av.x * wv.x; acc[0][1] += av.x * wv.y; acc[0][2] += av.x * wv.z; acc[0][3] += av.x * wv.w;
                acc[1][0] += av.y * wv.x; acc[1][1] += av.y * wv.y; acc[1][2] += av.y * wv.z; acc[1][3] += av.y * wv.w;
            }
        }
        __syncthreads();
    }
#pragma unroll
    for (int i = 0; i < TM; i++) {
        int gr = bm + ty * TM + i;
        if (gr >= M) continue;
        int id = 0;
        if (EPI == 2) id = addIdx[gr];
#pragma unroll
        for (int j = 0; j < 4; j++) {
            int gc = bn + tx * 4 + j;
            if (gc >= Nc) continue;
            float v = acc[i][j];
            if (EPI == 1)      v += bias[gc];
            else if (EPI == 2) v = fmaxf(v + addMat[(size_t)id * addStride + gc], 0.f);
            C[(size_t)gr * ldc + gc] = v;
        }
    }
}

// ---------------- software grid barrier ----------------
__device__ __forceinline__ void gbar(unsigned& target) {
    __syncthreads();
    target += GRID_LOOP;
    if (threadIdx.x == 0) {
        __threadfence();
        atomicAdd(&g_barc, 1u);
        while (*(volatile unsigned*)&g_barc < target) __nanosleep(20);
        __threadfence();
    }
    __syncthreads();
}

// ---------------- persistent recurrent loop (plain FFMA, resident W) -------
// dyn smem: sWz[256*32] | sWh[256*32] | sUr[256*32] | sA1[16*64] | sA2[16*64]
#define LOOP_SMEM ((3 * 256 * 32 + 2 * 16 * 64) * 4)
__global__ void __launch_bounds__(256, 1) k_loop(
    const int* __restrict__ word_ids, const int* __restrict__ h_nei,
    const float* __restrict__ Wz, const float* __restrict__ Wh,  // h-halves, ldw 512
    const float* __restrict__ Urw) {
    extern __shared__ float smem[];
    float* sWz = smem;
    float* sWh = smem + 8192;
    float* sUr = smem + 16384;
    float* sA1 = smem + 24576;   // [16][64]
    float* sA2 = smem + 25600;
    const int tid = threadIdx.x;
    const int bm = (blockIdx.x >> 3) * 64;
    const int bn = (blockIdx.x & 7) * 32;

    // one-time resident weight load (k-major: s[k*32+c] = W[(bn+c)*ldw + k])
    for (int idx = tid; idx < 8192; idx += 256) {
        int c = idx >> 8, k = idx & 255;
        sWz[k * 32 + c] = Wz[(size_t)(bn + c) * 512 + k];
        sWh[k * 32 + c] = Wh[(size_t)(bn + c) * 512 + k];
        sUr[k * 32 + c] = Urw[(size_t)(bn + c) * 256 + k];
    }
    __syncthreads();

    const int tx = tid & 7, ty = tid >> 3;       // 8x32 -> 32 cols x 64 rows
    const int lr = tid >> 2, lk = (tid & 3) << 2;
    unsigned target = 0;

    for (int t = 0; t < T_STEPS; t++) {
        // ---- phase 1: gather (sum_h, gated) ----
        for (int n = blockIdx.x; n < NN; n += GRID_LOOP) {
            int base = t * NN + n;
            int wid = word_ids[base];
            float rx = g_Epre[(size_t)wid * 1024 + 256 + tid];
            const int* hrow = h_nei + base * NB;
            float sh = 0.f, g = 0.f;
#pragma unroll
            for (int nb = 0; nb < NB; nb++) {
                int hi = hrow[nb];
                float v  = g_hbuf[(size_t)hi * H + tid];
                float rp = g_Urh[(size_t)hi * H + tid];
                sh += v;
                g  += v / (1.f + expf(-(rx + rp)));
            }
            g_sh[n * H + tid] = sh;
            g_xg[n * H + tid] = g;
        }
        gbar(target);

        // ---- phase 2: fused z/h GEMM + GRU combine (64 rows x 32 cols) ----
        float* hout = g_hbuf + (size_t)t * NN * H;
        {
            float accZ[2][4], accH[2][4];
#pragma unroll
            for (int i = 0; i < 2; i++)
#pragma unroll
                for (int j = 0; j < 4; j++) { accZ[i][j] = 0.f; accH[i][j] = 0.f; }
            const float* A1p = g_sh + (size_t)(bm + lr) * H + lk;
            const float* A2p = g_xg + (size_t)(bm + lr) * H + lk;
            for (int k0 = 0; k0 < H; k0 += 16) {
                float4 a1 = *(const float4*)(A1p + k0);
                float4 a2 = *(const float4*)(A2p + k0);
                sA1[(lk + 0) * 64 + lr] = a1.x; sA1[(lk + 1) * 64 + lr] = a1.y;
                sA1[(lk + 2) * 64 + lr] = a1.z; sA1[(lk + 3) * 64 + lr] = a1.w;
                sA2[(lk + 0) * 64 + lr] = a2.x; sA2[(lk + 1) * 64 + lr] = a2.y;
                sA2[(lk + 2) * 64 + lr] = a2.z; sA2[(lk + 3) * 64 + lr] = a2.w;
                __syncthreads();
#pragma unroll
                for (int k = 0; k < 16; k++) {
                    float2 a1v = *(const float2*)&sA1[k * 64 + ty * 2];
                    float2 a2v = *(const float2*)&sA2[k * 64 + ty * 2];
                    float4 wz = *(const float4*)&sWz[(k0 + k) * 32 + tx * 4];
                    float4 wh = *(const float4*)&sWh[(k0 + k) * 32 + tx * 4];
                    accZ[0][0] += a1v.x * wz.x; accZ[0][1] += a1v.x * wz.y;
                    accZ[0][2] += a1v.x * wz.z; accZ[0][3] += a1v.x * wz.w;
                    accZ[1][0] += a1v.y * wz.x; accZ[1][1] += a1v.y * wz.y;
                    accZ[1][2] += a1v.y * wz.z; accZ[1][3] += a1v.y * wz.w;
                    accH[0][0] += a2v.x * wh.x; accH[0][1] += a2v.x * wh.y;
                    accH[0][2] += a2v.x * wh.z; accH[0][3] += a2v.x * wh.w;
                    accH[1][0] += a2v.y * wh.x; accH[1][1] += a2v.y * wh.y;
                    accH[1][2] += a2v.y * wh.z; accH[1][3] += a2v.y * wh.w;
                }
                __syncthreads();
            }
            const int r0 = bm + ty * 2;
            int w0 = word_ids[t * NN + r0], w1 = word_ids[t * NN + r0 + 1];
            const float* e0 = g_Epre + (size_t)w0 * 1024;
            const float* e1 = g_Epre + (size_t)w1 * 1024;
            float o0[4], o1[4];
#pragma unroll
            for (int j = 0; j < 4; j++) {
                int c = bn + tx * 4 + j;
                float z0 = 1.f / (1.f + expf(-(accZ[0][j] + e0[c])));
                float z1 = 1.f / (1.f + expf(-(accZ[1][j] + e1[c])));
                float t0 = tanhf(accH[0][j] + e0[512 + c]);
                float t1 = tanhf(accH[1][j] + e1[512 + c]);
                o0[j] = (1.f - z0) * g_sh[(size_t)r0 * H + c] + z0 * t0;
                o1[j] = (1.f - z1) * g_sh[(size_t)(r0 + 1) * H + c] + z1 * t1;
            }
            *(float4*)&hout[(size_t)r0 * H + bn + tx * 4]       = make_float4(o0[0], o0[1], o0[2], o0[3]);
            *(float4*)&hout[(size_t)(r0 + 1) * H + bn + tx * 4] = make_float4(o1[0], o1[1], o1[2], o1[3]);
        }
        gbar(target);

        // ---- phase 3: Urh(t) = newh @ Ur^T (64 rows x 32 cols) ----
        float* uout = g_Urh + (size_t)t * NN * H;
        {
            float acc[2][4];
#pragma unroll
            for (int i = 0; i < 2; i++)
#pragma unroll
                for (int j = 0; j < 4; j++) acc[i][j] = 0.f;
            const float* Ap = hout + (size_t)(bm + lr) * H + lk;
            for (int k0 = 0; k0 < H; k0 += 16) {
                float4 a = *(const float4*)(Ap + k0);
                sA1[(lk + 0) * 64 + lr] = a.x; sA1[(lk + 1) * 64 + lr] = a.y;
                sA1[(lk + 2) * 64 + lr] = a.z; sA1[(lk + 3) * 64 + lr] = a.w;
                __syncthreads();
#pragma unroll
                for (int k = 0; k < 16; k++) {
                    float2 av = *(const float2*)&sA1[k * 64 + ty * 2];
                    float4 wv = *(const float4*)&sUr[(k0 + k) * 32 + tx * 4];
                    acc[0][0] += av.x * wv.x; acc[0][1] += av.x * wv.y;
                    acc[0][2] += av.x * wv.z; acc[0][3] += av.x * wv.w;
                    acc[1][0] += av.y * wv.x; acc[1][1] += av.y * wv.y;
                    acc[1][2] += av.y * wv.z; acc[1][3] += av.y * wv.w;
                }
                __syncthreads();
            }
            const int r0 = bm + ty * 2;
            *(float4*)&uout[(size_t)r0 * H + bn + tx * 4]       = make_float4(acc[0][0], acc[0][1], acc[0][2], acc[0][3]);
            *(float4*)&uout[(size_t)(r0 + 1) * H + bn + tx * 4] = make_float4(acc[1][0], acc[1][1], acc[1][2], acc[1][3]);
        }
        gbar(target);
    }
}

// ---------------- post-loop: cur_o for all edges ----------------
__global__ void k_curo(const int* __restrict__ o_nei) {
    int e = blockIdx.x, j = threadIdx.x;
    const int* orow = o_nei + e * NB;
    float co = 0.f;
#pragma unroll
    for (int nb = 0; nb < NB; nb++) co += g_hbuf[(size_t)orow[nb] * H + j];
    g_curo[(size_t)e * H + j] = co;
}

// ---------------- compact pred rows ----------------
__global__ void k_compact(const int* __restrict__ direction, const int* __restrict__ contexts) {
    __shared__ int warpsum[32];
    __shared__ int sbase;
    int tid = threadIdx.x, lane = tid & 31, w = tid >> 5;
    if (tid == 0) sbase = 0;
    __syncthreads();
    for (int chunk = 0; chunk < R; chunk += 1024) {
        int i = chunk + tid;
        int m = 0;
        if (i < R) m = (i < BB) ? 1 : (direction[i - BB] != 0);
        unsigned bal = __ballot_sync(0xffffffffu, m);
        int pre = __popc(bal & ((1u << lane) - 1u));
        if (lane == 0) warpsum[w] = __popc(bal);
        __syncthreads();
        if (tid < 32) {
            int v = warpsum[tid];
#pragma unroll
            for (int off = 1; off < 32; off <<= 1) {
                int o = __shfl_up_sync(0xffffffffu, v, off);
                if (tid >= off) v += o;
            }
            warpsum[tid] = v;
        }
        __syncthreads();
        int wbase = (w == 0) ? 0 : warpsum[w - 1];
        if (m) {
            int pos = sbase + wbase + pre;
            g_pidx[pos] = i;
            g_pctx[pos] = (i < BB) ? i : contexts[i - BB];
        }
        __syncthreads();
        if (tid == 0) sbase += warpsum[31];
        __syncthreads();
    }
    if (tid == 0) g_cnt = sbase;
}

// ---------------- build compacted pred A ----------------
__global__ void k_predAc() {
    int r = blockIdx.x;
    if (r >= g_cnt) return;
    int pi = g_pidx[r];
    int j = threadIdx.x;
    g_Ac[(size_t)r * H + j] = (pi < BB) ? 0.f : g_hbuf[(size_t)(pi - BB) * H + j];
}

// ---------------- pred row reduction ----------------
__global__ void k_predReduce(const int* __restrict__ pred_targets,
                             const int* __restrict__ root_word_ids) {
    int w = threadIdx.x >> 5, lane = threadIdx.x & 31;
    int r = blockIdx.x * 8 + w;
    if (r >= g_cnt) return;
    int gi = g_pidx[r];
    const float* row = g_big + (size_t)r * V;
    float bv = -INFINITY; int bi = 0x7fffffff;
    for (int j = lane; j < V; j += 32) {
        float v = row[j];
        if (v > bv) { bv = v; bi = j; }
    }
#pragma unroll
    for (int off = 16; off; off >>= 1) {
        float ov = __shfl_xor_sync(0xffffffffu, bv, off);
        int   oi = __shfl_xor_sync(0xffffffffu, bi, off);
        if (ov > bv || (ov == bv && oi < bi)) { bv = ov; bi = oi; }
    }
    float s = 0.f;
    for (int j = lane; j < V; j += 32) s += expf(row[j] - bv);
#pragma unroll
    for (int off = 16; off; off >>= 1) s += __shfl_xor_sync(0xffffffffu, s, off);
    if (lane == 0) {
        int tgt = (gi < BB) ? root_word_ids[gi] : pred_targets[gi - BB];
        g_rowNll[r] = bv + logf(s) - row[tgt];
        g_rowHit[r] = (bi == tgt) ? 1.f : 0.f;
    }
}

// ---------------- stop-head root rows ----------------
__global__ void k_stopRoot(const int* __restrict__ root_word_ids,
                           const int* __restrict__ root_o_idx,
                           const int* __restrict__ word_ids,
                           const int* __restrict__ contexts) {
    int b = blockIdx.x, j = threadIdx.x;
    float s = 0.f;
#pragma unroll
    for (int nb = 0; nb < NB; nb++) s += g_hbuf[(size_t)root_o_idx[b * NB + nb] * H + j];
    g_curo[(size_t)(E + b) * H + j] = s;
    if (j == 0) { g_swid[E + b] = root_word_ids[b]; g_sctx[E + b] = b; }
    // fill edge-row swid/sctx tables (strided across the BB blocks)
    for (int e = b * (E / BB) + j; e < (b + 1) * (E / BB); e += H) {
        g_swid[e] = word_ids[e];
        g_sctx[e] = contexts[e];
    }
}

// ---------------- stop scalar dot + bce ----------------
__global__ void k_stopDot(const float* __restrict__ Uo_w, const float* __restrict__ Uo_b,
                          const int* __restrict__ direction) {
    int w = threadIdx.x >> 5, lane = threadIdx.x & 31;
    int gi = blockIdx.x * 8 + w;
    if (gi >= R) return;
    const float* row = g_big + (size_t)gi * H;
    float s = 0.f;
#pragma unroll
    for (int k = lane; k < H; k += 32) s += row[k] * Uo_w[k];
#pragma unroll
    for (int off = 16; off; off >>= 1) s += __shfl_xor_sync(0xffffffffu, s, off);
    if (lane == 0) {
        s += Uo_b[0];
        float tgt = (gi < E) ? (float)direction[gi] : 0.f;
        g_rowBce[gi] = fmaxf(s, 0.f) - s * tgt + log1pf(expf(-fabsf(s)));
        float pred = (s >= 0.f) ? 1.f : 0.f;
        g_rowSAcc[gi] = (pred == tgt) ? 1.f : 0.f;
    }
}

// ---------------- final reduction ----------------
__global__ void k_final(float* __restrict__ out) {
    __shared__ float sm[1024];
    int tid = threadIdx.x;
    int cnt = g_cnt;
    float a0 = 0.f, a1 = 0.f, a3 = 0.f, a4 = 0.f;
    for (int i = tid; i < cnt; i += 1024) { a0 += g_rowNll[i]; a1 += g_rowHit[i]; }
    for (int i = tid; i < R; i += 1024)   { a3 += g_rowBce[i]; a4 += g_rowSAcc[i]; }
    auto red = [&](float v) -> float {
        sm[tid] = v; __syncthreads();
        for (int s = 512; s; s >>= 1) { if (tid < s) sm[tid] += sm[tid + s]; __syncthreads(); }
        float r = sm[0]; __syncthreads();
        return r;
    };
    float nll = red(a0), hit = red(a1), bce = red(a3), sac = red(a4);
    if (tid == 0) {
        out[0] = nll / (float)BB;
        out[1] = bce / (float)BB;
        out[2] = hit / (float)cnt;
        out[3] = sac / (float)R;
    }
}

// ---------------- launch ----------------
extern "C" void kernel_launch(void* const* d_in, const int* in_sizes, int n_in,
                              void* d_out, int out_size) {
    const float* emb    = (const float*)d_in[0];
    const float* W_z_w  = (const float*)d_in[1];
    const float* W_z_b  = (const float*)d_in[2];
    const float* W_r_w  = (const float*)d_in[3];
    const float* W_r_b  = (const float*)d_in[4];
    const float* U_r_w  = (const float*)d_in[5];
    const float* W_h_w  = (const float*)d_in[6];
    const float* W_h_b  = (const float*)d_in[7];
    const float* W_w    = (const float*)d_in[8];
    const float* W_b    = (const float*)d_in[9];
    const float* Wo_w   = (const float*)d_in[10];
    const float* Wo_b   = (const float*)d_in[11];
    const float* U_w    = (const float*)d_in[12];
    const float* U_b    = (const float*)d_in[13];
    const float* Ui_w   = (const float*)d_in[14];
    const float* Ui_b   = (const float*)d_in[15];
    const float* Uo_w   = (const float*)d_in[16];
    const float* Uo_b   = (const float*)d_in[17];
    const float* xtree  = (const float*)d_in[18];
    const int* word_ids = (const int*)d_in[19];
    const int* h_nei    = (const int*)d_in[20];
    const int* o_nei    = (const int*)d_in[21];
    const int* contexts = (const int*)d_in[22];
    const int* pred_t   = (const int*)d_in[23];
    const int* directn  = (const int*)d_in[24];
    const int* root_wid = (const int*)d_in[25];
    const int* root_oid = (const int*)d_in[26];
    float* out = (float*)d_out;

    float *p_Epre, *p_Xpu, *p_Wcat, *p_Wx, *p_bcat, *p_bcat2, *p_Ac, *p_h2, *p_big, *p_curo;
    int *p_cnt, *p_pctx, *p_swid, *p_sctx;
    cudaGetSymbolAddress((void**)&p_Epre, g_Epre);
    cudaGetSymbolAddress((void**)&p_Xpu, g_Xpu);
    cudaGetSymbolAddress((void**)&p_Wcat, g_Wcat);
    cudaGetSymbolAddress((void**)&p_Wx, g_Wx);
    cudaGetSymbolAddress((void**)&p_bcat, g_bcat);
    cudaGetSymbolAddress((void**)&p_bcat2, g_bcat2);
    cudaGetSymbolAddress((void**)&p_Ac, g_Ac);
    cudaGetSymbolAddress((void**)&p_h2, g_h2);
    cudaGetSymbolAddress((void**)&p_big, g_big);
    cudaGetSymbolAddress((void**)&p_curo, g_curo);
    cudaGetSymbolAddress((void**)&p_cnt, g_cnt);
    cudaGetSymbolAddress((void**)&p_pctx, g_pctx);
    cudaGetSymbolAddress((void**)&p_swid, g_swid);
    cudaGetSymbolAddress((void**)&p_sctx, g_sctx);

    static int smem_set = 0;
    if (!smem_set) {
        cudaFuncSetAttribute(k_loop, cudaFuncAttributeMaxDynamicSharedMemorySize, LOOP_SMEM);
        smem_set = 1;
    }

    // ---- one-time precomputes ----
    k_init<<<2, 256>>>();
    k_prep<<<1536, 256>>>(W_z_w, W_z_b, W_r_w, W_r_b, W_h_w, W_h_b, Ui_w, Ui_b,
                          W_w, W_b, U_w, U_b);
    // Epre = emb @ Wcat^T + bcat    (800 x 1024)
    k_gemm<64, 1><<<dim3(16, 13), 256>>>(emb, H, 800, nullptr, p_Wcat, H, 1024, H,
                                         p_bcat, p_Epre, 1024, nullptr, 0, nullptr);
    // Xpu = xtree @ Wx^T + bcat2    (256 x 512)
    k_gemm<64, 1><<<dim3(8, 4), 256>>>(xtree, LDIM, BB, nullptr, p_Wx, LDIM, 512, LDIM,
                                       p_bcat2, p_Xpu, 512, nullptr, 0, nullptr);

    // ---- persistent recurrent loop (plain FFMA, resident weights) ----
    k_loop<<<GRID_LOOP, 256, LOOP_SMEM>>>(word_ids, h_nei, W_z_w + 256, W_h_w + 256, U_r_w);

    // ---- cur_o for all edges (off the serial path) ----
    k_curo<<<E, 256>>>(o_nei);

    // ---- word prediction head (mask-compacted) ----
    k_compact<<<1, 1024>>>(directn, contexts);
    k_predAc<<<R, 256>>>();
    k_gemm<64, 2><<<dim3(4, 516), 256>>>(p_Ac, H, R, p_cnt, W_w, 384, H, H,
                                         nullptr, p_h2, H, p_Xpu, 512, p_pctx);
    k_gemm<64, 1><<<dim3(13, 516), 256>>>(p_h2, H, R, p_cnt, Wo_w, H, V, H,
                                          Wo_b, p_big, V, nullptr, 0, nullptr);
    k_predReduce<<<(R + 7) / 8, 256>>>(pred_t, root_wid);

    // ---- stop head ----
    k_stopRoot<<<BB, 256>>>(root_wid, root_oid, word_ids, contexts);
    k_gemm<64, 2><<<dim3(4, 516), 256>>>(p_curo, H, R, nullptr, Ui_w + 256, 512, H, H,
                                         nullptr, p_h2, H, p_Epre + 768, 1024, p_swid);
    k_gemm<64, 2><<<dim3(4, 516), 256>>>(p_h2, H, R, nullptr, U_w, 384, H, H,
                                         nullptr, p_big, H, p_Xpu + 256, 512, p_sctx);
    k_stopDot<<<(R + 7) / 8, 256>>>(Uo_w, Uo_b, directn);

    k_final<<<1, 1024>>>(out);
}

// round 7
// speedup vs baseline: 2.1700x; 1.4663x over previous
#include <cuda_runtime.h>
#include <math.h>

#define T_STEPS 32
#define NN      1024
#define H       256
#define LDIM    128
#define V       800
#define BB      256
#define NB      15
#define E       (T_STEPS * NN)   /* 32768 */
#define R       (E + BB)         /* 33024 */

// ---------------- device scratch ----------------
__device__ float g_hbuf[(E + 1) * H];
__device__ float g_Urh[(E + 1) * H];
__device__ float g_curo[(size_t)R * H];
__device__ float g_sh[NN * H];
__device__ float g_xg[NN * H];
__device__ float g_Epre[800 * 1024];   // [E_z|E_r|E_h|E_ui] per word, biases folded
__device__ float g_Xpu[BB * 512];      // [Xp|Xu] per context, biases folded
__device__ float g_Wcat[1024 * H];
__device__ float g_Wx[512 * LDIM];
__device__ float g_bcat[1024];
__device__ float g_bcat2[512];
__device__ float g_h2[(size_t)R * H];
__device__ float g_big[(size_t)R * V];
__device__ int   g_pidx[R];
__device__ int   g_pctx[R];
__device__ int   g_cnt;
__device__ float g_rowNll[R], g_rowHit[R], g_rowBce[R], g_rowSAcc[R];

// ---------------- init ----------------
__global__ void k_init() {
    int j = threadIdx.x;
    if (blockIdx.x == 0) g_hbuf[E * H + j] = 0.f;
    else                 g_Urh[E * H + j] = 0.f;
}

// ---------------- build combined weights ----------------
__global__ void k_prep(const float* __restrict__ Wz, const float* __restrict__ Wzb,
                       const float* __restrict__ Wr, const float* __restrict__ Wrb,
                       const float* __restrict__ Wh, const float* __restrict__ Whb,
                       const float* __restrict__ Ui, const float* __restrict__ Uib,
                       const float* __restrict__ Ww, const float* __restrict__ Wb,
                       const float* __restrict__ Uw, const float* __restrict__ Ub) {
    int r = blockIdx.x, j = threadIdx.x;
    if (r < 1024) {
        int rr = r & 255;
        float v, b;
        if (r < 256)      { v = Wz[rr * 512 + j]; b = Wzb[rr]; }
        else if (r < 512) { v = Wr[rr * 256 + j]; b = Wrb[rr]; }
        else if (r < 768) { v = Wh[rr * 512 + j]; b = Whb[rr]; }
        else              { v = Ui[rr * 512 + j]; b = Uib[rr]; }
        g_Wcat[r * H + j] = v;
        if (j == 0) g_bcat[r] = b;
    } else {
        int r2 = r - 1024;
        int rr = r2 & 255;
        if (j < LDIM)
            g_Wx[r2 * LDIM + j] = (r2 < 256) ? Ww[rr * 384 + 256 + j] : Uw[rr * 384 + 256 + j];
        if (j == 0) g_bcat2[r2] = (r2 < 256) ? Wb[rr] : Ub[rr];
    }
}

// ---------------- double-buffered fp32 GEMM: C = epi(A[M,K] @ W[Nc,K]^T) ---
// EPI: 0=plain 1=+bias 2=relu(+addMat[id])
// IM (EPI==2): 1 id=idxA[gr]; 2 id=gr<E?idxA[gr]:idxB[gr-E]; 3 id=gr<E?idxA[gr]:gr-E
// GA: A rows gathered from g_hbuf via gidx (pi<BB -> zero row)
template <int BM, int EPI, int IM, bool GA>
__global__ void __launch_bounds__(256) k_gemm(
    const float* __restrict__ A, int lda, int Mh, const int* __restrict__ Mptr,
    const float* __restrict__ W, int ldw, int Nc, int K,
    const float* __restrict__ bias,
    float* __restrict__ C, int ldc,
    const float* __restrict__ addMat, int addStride,
    const int* __restrict__ idxA, const int* __restrict__ idxB,
    const int* __restrict__ gidx) {
    const int M = Mptr ? *Mptr : Mh;
    const int bm = blockIdx.y * BM;
    if (bm >= M) return;
    const int bn = blockIdx.x * 64;
    __shared__ __align__(16) float sA[2][16][BM];
    __shared__ __align__(16) float sW[2][16][64];
    const int tid = threadIdx.x;
    constexpr int TM = BM / 16;
    const int tx = tid & 15, ty = tid >> 4;
    float acc[TM][4];
#pragma unroll
    for (int i = 0; i < TM; i++)
#pragma unroll
        for (int j = 0; j < 4; j++) acc[i][j] = 0.f;
    const int lr = tid >> 2, lk = (tid & 3) << 2;
    const bool wok = (bn + lr) < Nc;
    bool aok = (lr < BM) && ((bm + lr) < M);
    const float* Wp = W + (size_t)(bn + lr) * ldw + lk;
    const float* Ap = A;
    if (GA) {
        Ap = g_hbuf;
        if (aok) {
            int pi = gidx[bm + lr];
            if (pi < BB) aok = false;
            else Ap = g_hbuf + (size_t)(pi - BB) * H + lk;
        }
    } else {
        Ap = A + (size_t)(bm + (lr < BM ? lr : 0)) * lda + lk;
    }

    const int P = K / 16;
    const float4 z4 = make_float4(0.f, 0.f, 0.f, 0.f);
    float4 wR = wok ? *(const float4*)(Wp) : z4;
    float4 aR = z4;
    if (lr < BM) aR = aok ? *(const float4*)(Ap) : z4;
    sW[0][lk + 0][lr] = wR.x; sW[0][lk + 1][lr] = wR.y;
    sW[0][lk + 2][lr] = wR.z; sW[0][lk + 3][lr] = wR.w;
    if (lr < BM) {
        sA[0][lk + 0][lr] = aR.x; sA[0][lk + 1][lr] = aR.y;
        sA[0][lk + 2][lr] = aR.z; sA[0][lk + 3][lr] = aR.w;
    }
    __syncthreads();

    for (int p = 0; p < P; p++) {
        const int cb = p & 1, nb = cb ^ 1;
        if (p + 1 < P) {
            int k0 = (p + 1) * 16;
            wR = wok ? *(const float4*)(Wp + k0) : z4;
            if (lr < BM) aR = aok ? *(const float4*)(Ap + k0) : z4;
        }
#pragma unroll
        for (int k = 0; k < 16; k++) {
            float4 wv = *(const float4*)&sW[cb][k][tx * 4];
            if constexpr (TM == 4) {
                float4 av = *(const float4*)&sA[cb][k][ty * 4];
                acc[0][0] += av.x * wv.x; acc[0][1] += av.x * wv.y; acc[0][2] += av.x * wv.z; acc[0][3] += av.x * wv.w;
                acc[1][0] += av.y * wv.x; acc[1][1] += av.y * wv.y; acc[1][2] += av.y * wv.z; acc[1][3] += av.y * wv.w;
                acc[2][0] += av.z * wv.x; acc[2][1] += av.z * wv.y; acc[2][2] += av.z * wv.z; acc[2][3] += av.z * wv.w;
                acc[3][0] += av.w * wv.x; acc[3][1] += av.w * wv.y; acc[3][2] += av.w * wv.z; acc[3][3] += av.w * wv.w;
            } else {
                float2 av = *(const float2*)&sA[cb][k][ty * 2];
                acc[0][0] += av.x * wv.x; acc[0][1] += av.x * wv.y; acc[0][2] += av.x * wv.z; acc[0][3] += av.x * wv.w;
                acc[1][0] += av.y * wv.x; acc[1][1] += av.y * wv.y; acc[1][2] += av.y * wv.z; acc[1][3] += av.y * wv.w;
            }
        }
        if (p + 1 < P) {
            sW[nb][lk + 0][lr] = wR.x; sW[nb][lk + 1][lr] = wR.y;
            sW[nb][lk + 2][lr] = wR.z; sW[nb][lk + 3][lr] = wR.w;
            if (lr < BM) {
                sA[nb][lk + 0][lr] = aR.x; sA[nb][lk + 1][lr] = aR.y;
                sA[nb][lk + 2][lr] = aR.z; sA[nb][lk + 3][lr] = aR.w;
            }
            __syncthreads();
        }
    }

#pragma unroll
    for (int i = 0; i < TM; i++) {
        int gr = bm + ty * TM + i;
        if (gr >= M) continue;
        int id = 0;
        if (EPI == 2) {
            if (IM == 1)      id = idxA[gr];
            else if (IM == 2) id = (gr < E) ? idxA[gr] : idxB[gr - E];
            else              id = (gr < E) ? idxA[gr] : (gr - E);
        }
#pragma unroll
        for (int j = 0; j < 4; j++) {
            int gc = bn + tx * 4 + j;
            if (gc >= Nc) continue;
            float v = acc[i][j];
            if (EPI == 1)      v += bias[gc];
            else if (EPI == 2) v = fmaxf(v + addMat[(size_t)id * addStride + gc], 0.f);
            C[(size_t)gr * ldc + gc] = v;
        }
    }
}

// ---------------- per-step gather (h_nei only) ----------------
__global__ void k_gather(int t, const int* __restrict__ word_ids,
                         const int* __restrict__ h_nei) {
    __shared__ int s_hi[NB], s_wid;
    int n = blockIdx.x, j = threadIdx.x;
    int base = t * NN + n;
    if (j < NB) s_hi[j] = h_nei[base * NB + j];
    if (j == 0) s_wid = word_ids[base];
    __syncthreads();
    float rx = g_Epre[(size_t)s_wid * 1024 + 256 + j];
    float sh = 0.f, g = 0.f;
#pragma unroll
    for (int nb = 0; nb < NB; nb++) {
        int hi = s_hi[nb];
        float v  = g_hbuf[(size_t)hi * H + j];
        float rp = g_Urh[(size_t)hi * H + j];
        sh += v;
        g  += v / (1.f + expf(-(rx + rp)));
    }
    g_sh[n * H + j] = sh;
    g_xg[n * H + j] = g;
}

// ---------------- fused z/h GEMM + GRU combine (double-buffered) -----------
__global__ void __launch_bounds__(256) k_gemmZH(
    const float* __restrict__ Wzh, const float* __restrict__ Whh,  // h-halves, ldw 512
    const int* __restrict__ wid_t, float* __restrict__ hout) {
    const int bm = blockIdx.y * 32, bn = blockIdx.x * 64;
    __shared__ __align__(16) float sA1[2][16][32], sA2[2][16][32];
    __shared__ __align__(16) float sW1[2][16][64], sW2[2][16][64];
    const int tid = threadIdx.x;
    const int tx = tid & 15, ty = tid >> 4;
    float accZ[2][4], accH[2][4];
#pragma unroll
    for (int i = 0; i < 2; i++)
#pragma unroll
        for (int j = 0; j < 4; j++) { accZ[i][j] = 0.f; accH[i][j] = 0.f; }
    const int lr = tid >> 2, lk = (tid & 3) << 2;
    const int half = tid >> 7, lar = (tid & 127) >> 2;
    const float* Wzp = Wzh + (size_t)(bn + lr) * 512 + lk;
    const float* Whp = Whh + (size_t)(bn + lr) * 512 + lk;
    const float* Ap = (half ? g_xg : g_sh) + (size_t)(bm + lar) * H + lk;

    float4 w1R = *(const float4*)(Wzp);
    float4 w2R = *(const float4*)(Whp);
    float4 aR  = *(const float4*)(Ap);
    sW1[0][lk + 0][lr] = w1R.x; sW1[0][lk + 1][lr] = w1R.y;
    sW1[0][lk + 2][lr] = w1R.z; sW1[0][lk + 3][lr] = w1R.w;
    sW2[0][lk + 0][lr] = w2R.x; sW2[0][lk + 1][lr] = w2R.y;
    sW2[0][lk + 2][lr] = w2R.z; sW2[0][lk + 3][lr] = w2R.w;
    if (half) {
        sA2[0][lk + 0][lar] = aR.x; sA2[0][lk + 1][lar] = aR.y;
        sA2[0][lk + 2][lar] = aR.z; sA2[0][lk + 3][lar] = aR.w;
    } else {
        sA1[0][lk + 0][lar] = aR.x; sA1[0][lk + 1][lar] = aR.y;
        sA1[0][lk + 2][lar] = aR.z; sA1[0][lk + 3][lar] = aR.w;
    }
    __syncthreads();

    for (int p = 0; p < 16; p++) {
        const int cb = p & 1, nb = cb ^ 1;
        if (p < 15) {
            int k0 = (p + 1) * 16;
            w1R = *(const float4*)(Wzp + k0);
            w2R = *(const float4*)(Whp + k0);
            aR  = *(const float4*)(Ap + k0);
        }
#pragma unroll
        for (int k = 0; k < 16; k++) {
            float2 a1v = *(const float2*)&sA1[cb][k][ty * 2];
            float2 a2v = *(const float2*)&sA2[cb][k][ty * 2];
            float4 wz = *(const float4*)&sW1[cb][k][tx * 4];
            float4 wh = *(const float4*)&sW2[cb][k][tx * 4];
            accZ[0][0] += a1v.x * wz.x; accZ[0][1] += a1v.x * wz.y;
            accZ[0][2] += a1v.x * wz.z; accZ[0][3] += a1v.x * wz.w;
            accZ[1][0] += a1v.y * wz.x; accZ[1][1] += a1v.y * wz.y;
            accZ[1][2] += a1v.y * wz.z; accZ[1][3] += a1v.y * wz.w;
            accH[0][0] += a2v.x * wh.x; accH[0][1] += a2v.x * wh.y;
            accH[0][2] += a2v.x * wh.z; accH[0][3] += a2v.x * wh.w;
            accH[1][0] += a2v.y * wh.x; accH[1][1] += a2v.y * wh.y;
            accH[1][2] += a2v.y * wh.z; accH[1][3] += a2v.y * wh.w;
        }
        if (p < 15) {
            sW1[nb][lk + 0][lr] = w1R.x; sW1[nb][lk + 1][lr] = w1R.y;
            sW1[nb][lk + 2][lr] = w1R.z; sW1[nb][lk + 3][lr] = w1R.w;
            sW2[nb][lk + 0][lr] = w2R.x; sW2[nb][lk + 1][lr] = w2R.y;
            sW2[nb][lk + 2][lr] = w2R.z; sW2[nb][lk + 3][lr] = w2R.w;
            if (half) {
                sA2[nb][lk + 0][lar] = aR.x; sA2[nb][lk + 1][lar] = aR.y;
                sA2[nb][lk + 2][lar] = aR.z; sA2[nb][lk + 3][lar] = aR.w;
            } else {
                sA1[nb][lk + 0][lar] = aR.x; sA1[nb][lk + 1][lar] = aR.y;
                sA1[nb][lk + 2][lar] = aR.z; sA1[nb][lk + 3][lar] = aR.w;
            }
            __syncthreads();
        }
    }

    const int r0 = bm + ty * 2;
    int w0 = wid_t[r0], w1 = wid_t[r0 + 1];
    const float* e0 = g_Epre + (size_t)w0 * 1024;
    const float* e1 = g_Epre + (size_t)w1 * 1024;
    float o0[4], o1[4];
#pragma unroll
    for (int j = 0; j < 4; j++) {
        int c = bn + tx * 4 + j;
        float z0 = 1.f / (1.f + expf(-(accZ[0][j] + e0[c])));
        float z1 = 1.f / (1.f + expf(-(accZ[1][j] + e1[c])));
        float t0 = tanhf(accH[0][j] + e0[512 + c]);
        float t1 = tanhf(accH[1][j] + e1[512 + c]);
        o0[j] = (1.f - z0) * g_sh[(size_t)r0 * H + c] + z0 * t0;
        o1[j] = (1.f - z1) * g_sh[(size_t)(r0 + 1) * H + c] + z1 * t1;
    }
    *(float4*)&hout[(size_t)r0 * H + bn + tx * 4]       = make_float4(o0[0], o0[1], o0[2], o0[3]);
    *(float4*)&hout[(size_t)(r0 + 1) * H + bn + tx * 4] = make_float4(o1[0], o1[1], o1[2], o1[3]);
}

// ---------------- post-loop: cur_o for all edges ----------------
__global__ void k_curo(const int* __restrict__ o_nei) {
    int e = blockIdx.x, j = threadIdx.x;
    const int* orow = o_nei + e * NB;
    float co = 0.f;
#pragma unroll
    for (int nb = 0; nb < NB; nb++) co += g_hbuf[(size_t)orow[nb] * H + j];
    g_curo[(size_t)e * H + j] = co;
}

// ---------------- stop-head root rows ----------------
__global__ void k_stopRoot(const int* __restrict__ root_o_idx) {
    int b = blockIdx.x, j = threadIdx.x;
    float s = 0.f;
#pragma unroll
    for (int nb = 0; nb < NB; nb++) s += g_hbuf[(size_t)root_o_idx[b * NB + nb] * H + j];
    g_curo[(size_t)(E + b) * H + j] = s;
}

// ---------------- compact pred rows ----------------
__global__ void k_compact(const int* __restrict__ direction, const int* __restrict__ contexts) {
    __shared__ int warpsum[32];
    __shared__ int sbase;
    int tid = threadIdx.x, lane = tid & 31, w = tid >> 5;
    if (tid == 0) sbase = 0;
    __syncthreads();
    for (int chunk = 0; chunk < R; chunk += 1024) {
        int i = chunk + tid;
        int m = 0;
        if (i < R) m = (i < BB) ? 1 : (direction[i - BB] != 0);
        unsigned bal = __ballot_sync(0xffffffffu, m);
        int pre = __popc(bal & ((1u << lane) - 1u));
        if (lane == 0) warpsum[w] = __popc(bal);
        __syncthreads();
        if (tid < 32) {
            int v = warpsum[tid];
#pragma unroll
            for (int off = 1; off < 32; off <<= 1) {
                int o = __shfl_up_sync(0xffffffffu, v, off);
                if (tid >= off) v += o;
            }
            warpsum[tid] = v;
        }
        __syncthreads();
        int wbase = (w == 0) ? 0 : warpsum[w - 1];
        if (m) {
            int pos = sbase + wbase + pre;
            g_pidx[pos] = i;
            g_pctx[pos] = (i < BB) ? i : contexts[i - BB];
        }
        __syncthreads();
        if (tid == 0) sbase += warpsum[31];
        __syncthreads();
    }
    if (tid == 0) g_cnt = sbase;
}

// ---------------- pred row reduction ----------------
__global__ void k_predReduce(const int* __restrict__ pred_targets,
                             const int* __restrict__ root_word_ids) {
    int w = threadIdx.x >> 5, lane = threadIdx.x & 31;
    int r = blockIdx.x * 8 + w;
    if (r >= g_cnt) return;
    int gi = g_pidx[r];
    const float* row = g_big + (size_t)r * V;
    float bv = -INFINITY; int bi = 0x7fffffff;
    for (int j = lane; j < V; j += 32) {
        float v = row[j];
        if (v > bv) { bv = v; bi = j; }
    }
#pragma unroll
    for (int off = 16; off; off >>= 1) {
        float ov = __shfl_xor_sync(0xffffffffu, bv, off);
        int   oi = __shfl_xor_sync(0xffffffffu, bi, off);
        if (ov > bv || (ov == bv && oi < bi)) { bv = ov; bi = oi; }
    }
    float s = 0.f;
    for (int j = lane; j < V; j += 32) s += expf(row[j] - bv);
#pragma unroll
    for (int off = 16; off; off >>= 1) s += __shfl_xor_sync(0xffffffffu, s, off);
    if (lane == 0) {
        int tgt = (gi < BB) ? root_word_ids[gi] : pred_targets[gi - BB];
        g_rowNll[r] = bv + logf(s) - row[tgt];
        g_rowHit[r] = (bi == tgt) ? 1.f : 0.f;
    }
}

// ---------------- stop scalar dot + bce ----------------
__global__ void k_stopDot(const float* __restrict__ Uo_w, const float* __restrict__ Uo_b,
                          const int* __restrict__ direction) {
    int w = threadIdx.x >> 5, lane = threadIdx.x & 31;
    int gi = blockIdx.x * 8 + w;
    if (gi >= R) return;
    const float* row = g_big + (size_t)gi * H;
    float s = 0.f;
#pragma unroll
    for (int k = lane; k < H; k += 32) s += row[k] * Uo_w[k];
#pragma unroll
    for (int off = 16; off; off >>= 1) s += __shfl_xor_sync(0xffffffffu, s, off);
    if (lane == 0) {
        s += Uo_b[0];
        float tgt = (gi < E) ? (float)direction[gi] : 0.f;
        g_rowBce[gi] = fmaxf(s, 0.f) - s * tgt + log1pf(expf(-fabsf(s)));
        float pred = (s >= 0.f) ? 1.f : 0.f;
        g_rowSAcc[gi] = (pred == tgt) ? 1.f : 0.f;
    }
}

// ---------------- final reduction ----------------
__global__ void k_final(float* __restrict__ out) {
    __shared__ float sm[1024];
    int tid = threadIdx.x;
    int cnt = g_cnt;
    float a0 = 0.f, a1 = 0.f, a3 = 0.f, a4 = 0.f;
    for (int i = tid; i < cnt; i += 1024) { a0 += g_rowNll[i]; a1 += g_rowHit[i]; }
    for (int i = tid; i < R; i += 1024)   { a3 += g_rowBce[i]; a4 += g_rowSAcc[i]; }
    auto red = [&](float v) -> float {
        sm[tid] = v; __syncthreads();
        for (int s = 512; s; s >>= 1) { if (tid < s) sm[tid] += sm[tid + s]; __syncthreads(); }
        float r = sm[0]; __syncthreads();
        return r;
    };
    float nll = red(a0), hit = red(a1), bce = red(a3), sac = red(a4);
    if (tid == 0) {
        out[0] = nll / (float)BB;
        out[1] = bce / (float)BB;
        out[2] = hit / (float)cnt;
        out[3] = sac / (float)R;
    }
}

// ---------------- launch ----------------
extern "C" void kernel_launch(void* const* d_in, const int* in_sizes, int n_in,
                              void* d_out, int out_size) {
    const float* emb    = (const float*)d_in[0];
    const float* W_z_w  = (const float*)d_in[1];
    const float* W_z_b  = (const float*)d_in[2];
    const float* W_r_w  = (const float*)d_in[3];
    const float* W_r_b  = (const float*)d_in[4];
    const float* U_r_w  = (const float*)d_in[5];
    const float* W_h_w  = (const float*)d_in[6];
    const float* W_h_b  = (const float*)d_in[7];
    const float* W_w    = (const float*)d_in[8];
    const float* W_b    = (const float*)d_in[9];
    const float* Wo_w   = (const float*)d_in[10];
    const float* Wo_b   = (const float*)d_in[11];
    const float* U_w    = (const float*)d_in[12];
    const float* U_b    = (const float*)d_in[13];
    const float* Ui_w   = (const float*)d_in[14];
    const float* Ui_b   = (const float*)d_in[15];
    const float* Uo_w   = (const float*)d_in[16];
    const float* Uo_b   = (const float*)d_in[17];
    const float* xtree  = (const float*)d_in[18];
    const int* word_ids = (const int*)d_in[19];
    const int* h_nei    = (const int*)d_in[20];
    const int* o_nei    = (const int*)d_in[21];
    const int* contexts = (const int*)d_in[22];
    const int* pred_t   = (const int*)d_in[23];
    const int* directn  = (const int*)d_in[24];
    const int* root_wid = (const int*)d_in[25];
    const int* root_oid = (const int*)d_in[26];
    float* out = (float*)d_out;

    float *p_hbuf, *p_Urh, *p_Epre, *p_Xpu, *p_Wcat, *p_Wx, *p_bcat, *p_bcat2,
          *p_h2, *p_big, *p_curo;
    int *p_cnt, *p_pctx, *p_pidx;
    cudaGetSymbolAddress((void**)&p_hbuf, g_hbuf);
    cudaGetSymbolAddress((void**)&p_Urh, g_Urh);
    cudaGetSymbolAddress((void**)&p_Epre, g_Epre);
    cudaGetSymbolAddress((void**)&p_Xpu, g_Xpu);
    cudaGetSymbolAddress((void**)&p_Wcat, g_Wcat);
    cudaGetSymbolAddress((void**)&p_Wx, g_Wx);
    cudaGetSymbolAddress((void**)&p_bcat, g_bcat);
    cudaGetSymbolAddress((void**)&p_bcat2, g_bcat2);
    cudaGetSymbolAddress((void**)&p_h2, g_h2);
    cudaGetSymbolAddress((void**)&p_big, g_big);
    cudaGetSymbolAddress((void**)&p_curo, g_curo);
    cudaGetSymbolAddress((void**)&p_cnt, g_cnt);
    cudaGetSymbolAddress((void**)&p_pctx, g_pctx);
    cudaGetSymbolAddress((void**)&p_pidx, g_pidx);

    // ---- one-time precomputes ----
    k_init<<<2, 256>>>();
    k_prep<<<1536, 256>>>(W_z_w, W_z_b, W_r_w, W_r_b, W_h_w, W_h_b, Ui_w, Ui_b,
                          W_w, W_b, U_w, U_b);
    // Epre = emb @ Wcat^T + bcat    (800 x 1024)
    k_gemm<64, 1, 0, false><<<dim3(16, 13), 256>>>(emb, H, 800, nullptr, p_Wcat, H, 1024, H,
                                                   p_bcat, p_Epre, 1024, nullptr, 0,
                                                   nullptr, nullptr, nullptr);
    // Xpu = xtree @ Wx^T + bcat2    (256 x 512)
    k_gemm<64, 1, 0, false><<<dim3(8, 4), 256>>>(xtree, LDIM, BB, nullptr, p_Wx, LDIM, 512, LDIM,
                                                 p_bcat2, p_Xpu, 512, nullptr, 0,
                                                 nullptr, nullptr, nullptr);

    // ---- recurrent loop: 3 launches/step ----
    for (int t = 0; t < T_STEPS; t++) {
        k_gather<<<NN, 256>>>(t, word_ids, h_nei);
        k_gemmZH<<<dim3(4, 32), 256>>>(W_z_w + 256, W_h_w + 256, word_ids + t * NN,
                                       p_hbuf + (size_t)t * NN * H);
        k_gemm<32, 0, 0, false><<<dim3(4, 32), 256>>>(p_hbuf + (size_t)t * NN * H, H, NN, nullptr,
                                                      U_r_w, H, H, H, nullptr,
                                                      p_Urh + (size_t)t * NN * H, H, nullptr, 0,
                                                      nullptr, nullptr, nullptr);
    }

    // ---- cur_o for all edges (off the serial path) ----
    k_curo<<<E, 256>>>(o_nei);

    // ---- word prediction head (mask-compacted, gathered A) ----
    k_compact<<<1, 1024>>>(directn, contexts);
    k_gemm<64, 2, 1, true><<<dim3(4, 516), 256>>>(nullptr, H, R, p_cnt, W_w, 384, H, H,
                                                  nullptr, p_h2, H, p_Xpu, 512,
                                                  p_pctx, nullptr, p_pidx);
    k_gemm<64, 1, 0, false><<<dim3(13, 516), 256>>>(p_h2, H, R, p_cnt, Wo_w, H, V, H,
                                                    Wo_b, p_big, V, nullptr, 0,
                                                    nullptr, nullptr, nullptr);
    k_predReduce<<<(R + 7) / 8, 256>>>(pred_t, root_wid);

    // ---- stop head ----
    k_stopRoot<<<BB, 256>>>(root_oid);
    k_gemm<64, 2, 2, false><<<dim3(4, 516), 256>>>(p_curo, H, R, nullptr, Ui_w + 256, 512, H, H,
                                                   nullptr, p_h2, H, p_Epre + 768, 1024,
                                                   word_ids, root_wid, nullptr);
    k_gemm<64, 2, 3, false><<<dim3(4, 516), 256>>>(p_h2, H, R, nullptr, U_w, 384, H, H,
                                                   nullptr, p_big, H, p_Xpu + 256, 512,
                                                   contexts, nullptr, nullptr);
    k_stopDot<<<(R + 7) / 8, 256>>>(Uo_w, Uo_b, directn);

    k_final<<<1, 1024>>>(out);
}